// round 2
// baseline (speedup 1.0000x reference)
#include <cuda_runtime.h>
#include <cstdint>
#include <math.h>

#define NMAX 262144
#define GMAX 8192
#define EDIM 118
#define FDIM 128
#define PITCH 132   // smem row pitch in 4B words (conflict-free fragments)

// ---------------- scratch (device globals; no allocation) ----------------
__device__ float g_y[NMAX];
__device__ float g_denom[GMAX];
__device__ float g_dot[EDIM * 2];

// ---------------- helpers ----------------
__device__ __forceinline__ uint32_t f2tf32(float x) {
    uint32_t u;
    asm("cvt.rna.tf32.f32 %0, %1;" : "=r"(u) : "f"(x));
    return u;
}
__device__ __forceinline__ float silu_f(float x) {
    return x / (1.f + __expf(-x));
}
__device__ __forceinline__ void mma8(float* c,
                                     uint32_t a0, uint32_t a1, uint32_t a2, uint32_t a3,
                                     uint32_t b0, uint32_t b1) {
    asm volatile(
        "mma.sync.aligned.m16n8k8.row.col.f32.tf32.tf32.f32 "
        "{%0,%1,%2,%3}, {%4,%5,%6,%7}, {%8,%9}, {%0,%1,%2,%3};"
        : "+f"(c[0]), "+f"(c[1]), "+f"(c[2]), "+f"(c[3])
        : "r"(a0), "r"(a1), "r"(a2), "r"(a3), "r"(b0), "r"(b1));
}

// ---------------- kernel 0: zero denom ----------------
__global__ void k_zero(int G) {
    int i = blockIdx.x * blockDim.x + threadIdx.x;
    if (i < G) g_denom[i] = 0.f;
}

// ---------------- kernel 1: dot_table[e][r] = sum_f Wq[f,e]*Wk[r,f] ----------------
__global__ void k_dot(const float* __restrict__ Wq, const float* __restrict__ Wk) {
    __shared__ float sk[2 * FDIM];
    int t = threadIdx.x;
    if (t < 2 * FDIM) sk[t] = Wk[t];
    __syncthreads();
    if (t < EDIM) {
        float a0 = 0.f, a1 = 0.f;
#pragma unroll 8
        for (int f = 0; f < FDIM; ++f) {
            float w = Wq[f * EDIM + t];  // coalesced across threads
            a0 += w * sk[f];
            a1 += w * sk[FDIM + f];
        }
        g_dot[t * 2 + 0] = a0;
        g_dot[t * 2 + 1] = a1;
    }
}

// ---------------- kernel 2: warp-per-atom: z, y, denom ----------------
__global__ void k_scan(const float* __restrict__ oh, const float* __restrict__ psi,
                       const int* __restrict__ bs, int N) {
    int warp = (blockIdx.x * blockDim.x + threadIdx.x) >> 5;
    int lane = threadIdx.x & 31;
    if (warp >= N) return;
    const float* row = oh + (size_t)warp * EDIM;
    int z = -1;
#pragma unroll
    for (int j = 0; j < 4; ++j) {
        int e = lane + 32 * j;
        if (e < EDIM) {
            if (row[e] > 0.5f) z = e;
        }
    }
    z = __reduce_max_sync(0xffffffffu, z);
    if (lane == 0) {
        int g = bs[warp];
        float p = psi[g];
        int r = (p < 0.f) ? 1 : 0;
        float qk = g_dot[z * 2 + r] * 0.08838834764831845f;  // 1/sqrt(128)
        float y = (qk > 20.f) ? qk : log1pf(expf(qk));
        g_y[warp] = y;
        atomicAdd(&g_denom[g], y);
    }
}

// ---------------- kernel 3: fused att + MLP (tf32 tensor cores) ----------------
extern __shared__ unsigned char smem_raw[];

__global__ void __launch_bounds__(256, 1)
k_mlp(const float* __restrict__ psi, const float* __restrict__ Wv,
      const float* __restrict__ W1, const float* __restrict__ W2,
      const int* __restrict__ bs, float* __restrict__ out, int N) {
    uint32_t* sW1 = (uint32_t*)smem_raw;              // [128][PITCH] tf32
    uint32_t* sW2 = sW1 + PITCH * FDIM;               // [128][PITCH] tf32
    uint32_t* sA2 = sW2 + PITCH * FDIM;               // [128][PITCH] tf32 / reused as f32 out
    float* sAtt = (float*)(sA2 + PITCH * FDIM);       // [128]
    float* sWv = sAtt + 128;                          // [2][128]
    int* sR = (int*)(sWv + 256);                      // [128]

    int tid = threadIdx.x;
    int base = blockIdx.x * 128;

    // load W1, W2 -> smem (tf32)
    const float4* W1v = (const float4*)W1;
    const float4* W2v = (const float4*)W2;
#pragma unroll
    for (int it = 0; it < 16; ++it) {
        int fidx = tid + it * 256;   // 0..4095
        int r = fidx >> 5;
        int c = (fidx & 31) * 4;
        float4 v1 = W1v[fidx];
        float4 v2 = W2v[fidx];
        uint32_t* p1 = sW1 + r * PITCH + c;
        p1[0] = f2tf32(v1.x); p1[1] = f2tf32(v1.y); p1[2] = f2tf32(v1.z); p1[3] = f2tf32(v1.w);
        uint32_t* p2 = sW2 + r * PITCH + c;
        p2[0] = f2tf32(v2.x); p2[1] = f2tf32(v2.y); p2[2] = f2tf32(v2.z); p2[3] = f2tf32(v2.w);
    }
    sWv[tid] = Wv[tid];  // 256 = 2*128
    if (tid < 128) {
        int n = base + tid;
        float att = 0.f;
        int r = 0;
        if (n < N) {
            int g = bs[n];
            float p = psi[g];
            r = (p < 0.f) ? 1 : 0;
            att = p * g_y[n] / (g_denom[g] + 1e-6f);
        }
        sAtt[tid] = att;
        sR[tid] = r;
    }
    __syncthreads();

    int lane = tid & 31, w = tid >> 5;
    int g8 = lane >> 2, t4 = lane & 3;
    int row0 = w * 16 + g8, row1 = row0 + 8;
    float att0 = sAtt[row0], att1 = sAtt[row1];
    const float* wv0 = sWv + sR[row0] * 128;
    const float* wv1 = sWv + sR[row1] * 128;

    float acc[16][4];
#pragma unroll
    for (int nb = 0; nb < 16; ++nb) {
        acc[nb][0] = acc[nb][1] = acc[nb][2] = acc[nb][3] = 0.f;
    }

    // GEMM1: h1[i,n] = sum_k silu(att_i*wv_{r_i}[k]) * W1[n,k]
#pragma unroll
    for (int kb = 0; kb < 16; ++kb) {
        int k0 = kb * 8 + t4, k1 = k0 + 4;
        uint32_t a0 = f2tf32(silu_f(att0 * wv0[k0]));
        uint32_t a1 = f2tf32(silu_f(att1 * wv1[k0]));
        uint32_t a2 = f2tf32(silu_f(att0 * wv0[k1]));
        uint32_t a3 = f2tf32(silu_f(att1 * wv1[k1]));
#pragma unroll
        for (int nb = 0; nb < 16; ++nb) {
            const uint32_t* bp = sW1 + (nb * 8 + g8) * PITCH;
            mma8(acc[nb], a0, a1, a2, a3, bp[k0], bp[k1]);
        }
    }

    // A2 = tf32(silu(h1))  (warp-local rows only)
#pragma unroll
    for (int nb = 0; nb < 16; ++nb) {
        int c0 = nb * 8 + 2 * t4;
        sA2[row0 * PITCH + c0    ] = f2tf32(silu_f(acc[nb][0]));
        sA2[row0 * PITCH + c0 + 1] = f2tf32(silu_f(acc[nb][1]));
        sA2[row1 * PITCH + c0    ] = f2tf32(silu_f(acc[nb][2]));
        sA2[row1 * PITCH + c0 + 1] = f2tf32(silu_f(acc[nb][3]));
    }
    __syncwarp();

    float acc2[16][4];
#pragma unroll
    for (int nb = 0; nb < 16; ++nb) {
        acc2[nb][0] = acc2[nb][1] = acc2[nb][2] = acc2[nb][3] = 0.f;
    }

    // GEMM2: h2 = A2 @ W2^T
#pragma unroll
    for (int kb = 0; kb < 16; ++kb) {
        int k0 = kb * 8 + t4, k1 = k0 + 4;
        uint32_t a0 = sA2[row0 * PITCH + k0];
        uint32_t a1 = sA2[row1 * PITCH + k0];
        uint32_t a2 = sA2[row0 * PITCH + k1];
        uint32_t a3 = sA2[row1 * PITCH + k1];
#pragma unroll
        for (int nb = 0; nb < 16; ++nb) {
            const uint32_t* bp = sW2 + (nb * 8 + g8) * PITCH;
            mma8(acc2[nb], a0, a1, a2, a3, bp[k0], bp[k1]);
        }
    }
    __syncwarp();

    // epilogue: out = v_att + h2 (stage in smem for coalesced store)
    float* sOut = (float*)sA2;
#pragma unroll
    for (int nb = 0; nb < 16; ++nb) {
        int c0 = nb * 8 + 2 * t4;
        sOut[row0 * PITCH + c0    ] = att0 * wv0[c0]     + acc2[nb][0];
        sOut[row0 * PITCH + c0 + 1] = att0 * wv0[c0 + 1] + acc2[nb][1];
        sOut[row1 * PITCH + c0    ] = att1 * wv1[c0]     + acc2[nb][2];
        sOut[row1 * PITCH + c0 + 1] = att1 * wv1[c0 + 1] + acc2[nb][3];
    }
    __syncthreads();

#pragma unroll
    for (int it = 0; it < 16; ++it) {
        int fidx = tid + it * 256;
        int r = fidx >> 5;
        int c = (fidx & 31) * 4;
        int n = base + r;
        if (n < N) {
            float4 v;
            v.x = sOut[r * PITCH + c];
            v.y = sOut[r * PITCH + c + 1];
            v.z = sOut[r * PITCH + c + 2];
            v.w = sOut[r * PITCH + c + 3];
            ((float4*)out)[(size_t)n * 32 + (c >> 2)] = v;
        }
    }
}

// ---------------- launch ----------------
extern "C" void kernel_launch(void* const* d_in, const int* in_sizes, int n_in,
                              void* d_out, int out_size) {
    const float* oh  = (const float*)d_in[0];
    const float* psi = (const float*)d_in[1];
    const float* Wq  = (const float*)d_in[2];
    const float* Wk  = (const float*)d_in[3];
    const float* Wv  = (const float*)d_in[4];
    const float* W1  = (const float*)d_in[5];
    const float* W2  = (const float*)d_in[6];
    const int*   bs  = (const int*)d_in[7];
    int N = in_sizes[7];
    int G = in_sizes[1];
    float* out = (float*)d_out;

    const int smem_bytes = (3 * PITCH * FDIM) * 4 + 128 * 4 + 256 * 4 + 128 * 4;
    cudaFuncSetAttribute(k_mlp, cudaFuncAttributeMaxDynamicSharedMemorySize, smem_bytes);

    k_zero<<<(G + 255) / 256, 256>>>(G);
    k_dot<<<1, 256>>>(Wq, Wk);
    k_scan<<<(N + 7) / 8, 256>>>(oh, psi, bs, N);
    k_mlp<<<(N + 127) / 128, 256, smem_bytes>>>(psi, Wv, W1, W2, bs, out, N);
}

// round 5
// speedup vs baseline: 2.1664x; 2.1664x over previous
#include <cuda_runtime.h>
#include <cstdint>
#include <math.h>

#define NMAX 262144
#define GMAX 8192
#define EDIM 118
#define FDIM 128
#define MNODE 64          // Chebyshev nodes per branch
#define JDEG  32          // Chebyshev coefficients kept per branch

// ---------------- scratch (device globals; no allocation) ----------------
__device__ float    g_y[NMAX];
__device__ float    g_denom[GMAX];
__device__ float    g_dot[EDIM * 2];
__device__ float    g_amax;
__device__ double   g_nodes[2 * MNODE * FDIM];   // G(att) residual at Chebyshev nodes (fp64)
__device__ uint32_t g_coef[FDIM * 64];           // tf32 G-coeffs, layout [f][r*32+j]
__device__ float    g_lin[2 * FDIM];             // F'(0) per branch (fp32)

// ---------------- helpers ----------------
__device__ __forceinline__ uint32_t f2tf32(float x) {
    uint32_t u;
    asm("cvt.rna.tf32.f32 %0, %1;" : "=r"(u) : "f"(x));
    return u;
}
__device__ __forceinline__ double silu_d(double x) {
    return x / (1.0 + exp(-x));
}
__device__ __forceinline__ void mma8(float* c,
                                     uint32_t a0, uint32_t a1, uint32_t a2, uint32_t a3,
                                     uint32_t b0, uint32_t b1) {
    asm volatile(
        "mma.sync.aligned.m16n8k8.row.col.f32.tf32.tf32.f32 "
        "{%0,%1,%2,%3}, {%4,%5,%6,%7}, {%8,%9}, {%0,%1,%2,%3};"
        : "+f"(c[0]), "+f"(c[1]), "+f"(c[2]), "+f"(c[3])
        : "r"(a0), "r"(a1), "r"(a2), "r"(a3), "r"(b0), "r"(b1));
}

// ---------------- kernel: zero denom ----------------
__global__ void k_zero(int G) {
    int i = blockIdx.x * blockDim.x + threadIdx.x;
    if (i < G) g_denom[i] = 0.f;
}

// ---------------- kernel: dot table + amax ----------------
__global__ void k_prep(const float* __restrict__ Wq, const float* __restrict__ Wk,
                       const float* __restrict__ psi, int G) {
    __shared__ float sk[256];
    __shared__ float smax[8];
    int t = threadIdx.x;
    sk[t] = Wk[t];
    float m = 0.f;
    for (int i = t; i < G; i += 256) m = fmaxf(m, fabsf(psi[i]));
#pragma unroll
    for (int o = 16; o; o >>= 1) m = fmaxf(m, __shfl_xor_sync(0xffffffffu, m, o));
    if ((t & 31) == 0) smax[t >> 5] = m;
    __syncthreads();
    if (t == 0) {
        float mm = 1e-12f;
        for (int i = 0; i < 8; ++i) mm = fmaxf(mm, smax[i]);
        g_amax = mm;
    }
    if (t < EDIM) {
        float a0 = 0.f, a1 = 0.f;
#pragma unroll 8
        for (int f = 0; f < FDIM; ++f) {
            float w = Wq[f * EDIM + t];
            a0 = fmaf(w, sk[f], a0);
            a1 = fmaf(w, sk[FDIM + f], a1);
        }
        g_dot[t * 2 + 0] = a0;
        g_dot[t * 2 + 1] = a1;
    }
}

// ---------------- kernel: early-exit one-hot scan -> y, denom ----------------
__global__ void k_scan(const float* __restrict__ oh, const float* __restrict__ psi,
                       const int* __restrict__ bs, int N) {
    int warp = (blockIdx.x * blockDim.x + threadIdx.x) >> 5;
    int lane = threadIdx.x & 31;
    if (warp >= N) return;
    const float* row = oh + (size_t)warp * EDIM;
    float v0 = __ldcs(row + lane);
    float v1 = __ldcs(row + 32 + lane);
    unsigned m0 = __ballot_sync(0xffffffffu, v0 > 0.5f);
    unsigned m1 = __ballot_sync(0xffffffffu, v1 > 0.5f);
    int z;
    if (m0) z = __ffs(m0) - 1;
    else if (m1) z = 31 + __ffs(m1);
    else {
        float v2 = __ldcs(row + 64 + lane);
        int e3 = 96 + lane;
        float v3 = (e3 < EDIM) ? __ldcs(row + e3) : 0.f;
        m0 = __ballot_sync(0xffffffffu, v2 > 0.5f);
        m1 = __ballot_sync(0xffffffffu, v3 > 0.5f);
        z = m0 ? (63 + __ffs(m0)) : (95 + __ffs(m1));
    }
    if (lane == 0) {
        int g = bs[warp];
        float p = psi[g];
        int r = (p < 0.f) ? 1 : 0;
        float qk = g_dot[z * 2 + r] * 0.08838834764831845f;  // 1/sqrt(128)
        float y = (qk > 20.f) ? qk : log1pf(expf(qk));
        g_y[warp] = y;
        atomicAdd(&g_denom[g], y);
    }
}

// ---------------- kernel: fp64 MLP at Chebyshev nodes -> residual G + F'(0) ----
// row = r*MNODE + m.  F(a) = a*wv_r + MLP(silu(a*wv_r))
// F1 = wv + 0.25 * W2 @ (W1 @ wv)           (exact Jacobian at 0)
// G(a) = (F(a) - a*F1)/a^2 = (g - 0.25*a*gl)/a^2
__global__ void k_nodes(const float* __restrict__ Wv, const float* __restrict__ W1,
                        const float* __restrict__ W2) {
    extern __shared__ double smd[];
    double* sW  = smd;                  // [128][132]
    double* sx  = sW + FDIM * 132;      // [128] silu(a*wv)
    double* swv = sx + FDIM;            // [128] wv
    double* shl = swv + FDIM;           // [128] W1@wv
    double* sh  = shl + FDIM;           // [128] silu(h)
    int row = blockIdx.x;
    int r = row >> 6, m = row & 63;
    int t = threadIdx.x;                // 128 threads
    double amax = (double)g_amax;
    double c = cospi((2.0 * m + 1.0) / (2.0 * MNODE));
    double a = (r == 0) ? amax * (c + 1.0) * 0.5 : amax * (c - 1.0) * 0.5;
    double wv = (double)Wv[r * FDIM + t];
    sx[t] = silu_d(a * wv);
    swv[t] = wv;
    // W1 -> smem fp64
    const float4* W1v = (const float4*)W1;
    for (int i = t; i < FDIM * 32; i += 128) {
        float4 v = W1v[i];
        double* p = sW + (i >> 5) * 132 + (i & 31) * 4;
        p[0] = v.x; p[1] = v.y; p[2] = v.z; p[3] = v.w;
    }
    __syncthreads();
    double h = 0.0, hl = 0.0;
#pragma unroll 4
    for (int k = 0; k < FDIM; ++k) {
        double w = sW[t * 132 + k];
        h  = fma(sx[k],  w, h);
        hl = fma(swv[k], w, hl);
    }
    sh[t] = silu_d(h);
    shl[t] = hl;
    __syncthreads();
    const float4* W2v = (const float4*)W2;
    for (int i = t; i < FDIM * 32; i += 128) {
        float4 v = W2v[i];
        double* p = sW + (i >> 5) * 132 + (i & 31) * 4;
        p[0] = v.x; p[1] = v.y; p[2] = v.z; p[3] = v.w;
    }
    __syncthreads();
    double g = 0.0, gl = 0.0;
#pragma unroll 4
    for (int k = 0; k < FDIM; ++k) {
        double w = sW[t * 132 + k];
        g  = fma(sh[k],  w, g);
        gl = fma(shl[k], w, gl);
    }
    g_nodes[row * FDIM + t] = (g - 0.25 * a * gl) / (a * a);
    if (m == 0) g_lin[r * FDIM + t] = (float)(wv + 0.25 * gl);
}

// ---------------- kernel: fp64 DCT -> tf32 Chebyshev coefficients of G --------
__global__ void k_cheb() {
    int id = blockIdx.x * blockDim.x + threadIdx.x;   // 8192
    int f = id & 127;
    int j = (id >> 7) & 31;
    int r = id >> 12;
    double s = 0.0;
#pragma unroll 8
    for (int m = 0; m < MNODE; ++m) {
        double ck = cospi((double)(j * (2 * m + 1)) / (double)(2 * MNODE));
        s = fma(g_nodes[(r * MNODE + m) * FDIM + f], ck, s);
    }
    double cj = s * ((j == 0) ? (1.0 / MNODE) : (2.0 / MNODE));
    g_coef[f * 64 + r * 32 + j] = f2tf32((float)cj);
}

// ---------------- kernel: fused att + conditioned-Chebyshev GEMM output ------
extern __shared__ unsigned char smem_raw[];

__global__ void __launch_bounds__(256, 2)
k_out(const float* __restrict__ psi, const int* __restrict__ bs,
      float* __restrict__ out, int N, int ntiles) {
    uint32_t* sC = (uint32_t*)smem_raw;   // [128][68] G-coeffs (f-major)
    uint32_t* sA = sC + FDIM * 68;        // [64][132]  att^2 * T-basis (k-major)
    float* sF1  = (float*)(sA + 64 * 132); // [2][128]
    float* sAtt = sF1 + 256;               // [128]
    int*   sR   = (int*)(sAtt + 128);      // [128]
    int tid = threadIdx.x;
    for (int idx = tid; idx < FDIM * 64; idx += 256) {
        int f = idx >> 6, kk = idx & 63;
        sC[f * 68 + kk] = g_coef[idx];
    }
    if (tid < 256) sF1[tid] = g_lin[tid];
    float amax = g_amax;
    float inv2 = 2.f / amax;
    int lane = tid & 31, w = tid >> 5;
    int g8 = lane >> 2, t4 = lane & 3;
    int row0 = w * 16 + g8, row1 = row0 + 8;

    for (int tile = blockIdx.x; tile < ntiles; tile += gridDim.x) {
        __syncthreads();
        for (int i = tid; i < 64 * 132; i += 256) sA[i] = 0u;
        __syncthreads();
        if (tid < 128) {
            int n = tile * 128 + tid;
            float att = 0.f;
            int r = 0;
            if (n < N) {
                int g = bs[n];
                float p = psi[g];
                float y = g_y[n];
                att = p * y / (g_denom[g] + 1e-6f);
                r = (p < 0.f) ? 1 : 0;
                float u = fmaf(att, inv2, r ? 1.f : -1.f);
                u = fminf(fmaxf(u, -1.f), 1.f);
                float att2 = att * att;
                int base = r * 32;
                sA[(base + 0) * 132 + tid] = f2tf32(att2);        // att^2*T0
                sA[(base + 1) * 132 + tid] = f2tf32(att2 * u);    // att^2*T1
                float t0 = 1.f, t1 = u, twou = u + u;
#pragma unroll
                for (int j = 2; j < JDEG; ++j) {
                    float t2 = fmaf(twou, t1, -t0);
                    sA[(base + j) * 132 + tid] = f2tf32(att2 * t2);
                    t0 = t1; t1 = t2;
                }
            }
            sAtt[tid] = att;
            sR[tid] = r;
        }
        __syncthreads();

        float acc[16][4];
#pragma unroll
        for (int nb = 0; nb < 16; ++nb) {
            acc[nb][0] = acc[nb][1] = acc[nb][2] = acc[nb][3] = 0.f;
        }
#pragma unroll
        for (int kb = 0; kb < 8; ++kb) {
            int k0 = kb * 8 + t4, k1 = k0 + 4;
            uint32_t a0 = sA[k0 * 132 + row0];
            uint32_t a1 = sA[k0 * 132 + row1];
            uint32_t a2 = sA[k1 * 132 + row0];
            uint32_t a3 = sA[k1 * 132 + row1];
#pragma unroll
            for (int nb = 0; nb < 16; ++nb) {
                const uint32_t* bp = sC + (nb * 8 + g8) * 68;
                mma8(acc[nb], a0, a1, a2, a3, bp[k0], bp[k1]);
            }
        }
        float att0 = sAtt[row0], att1 = sAtt[row1];
        const float* f10 = sF1 + sR[row0] * FDIM;
        const float* f11 = sF1 + sR[row1] * FDIM;
        int n0 = tile * 128 + row0;
        int n1 = n0 + 8;
        if (n0 < N) {
#pragma unroll
            for (int nb = 0; nb < 16; ++nb) {
                int c0 = nb * 8 + 2 * t4;
                float2 v;
                v.x = fmaf(att0, f10[c0],     acc[nb][0]);
                v.y = fmaf(att0, f10[c0 + 1], acc[nb][1]);
                ((float2*)out)[((size_t)n0 * 128 + c0) >> 1] = v;
            }
        }
        if (n1 < N) {
#pragma unroll
            for (int nb = 0; nb < 16; ++nb) {
                int c0 = nb * 8 + 2 * t4;
                float2 v;
                v.x = fmaf(att1, f11[c0],     acc[nb][2]);
                v.y = fmaf(att1, f11[c0 + 1], acc[nb][3]);
                ((float2*)out)[((size_t)n1 * 128 + c0) >> 1] = v;
            }
        }
    }
}

// ---------------- launch ----------------
extern "C" void kernel_launch(void* const* d_in, const int* in_sizes, int n_in,
                              void* d_out, int out_size) {
    const float* oh  = (const float*)d_in[0];
    const float* psi = (const float*)d_in[1];
    const float* Wq  = (const float*)d_in[2];
    const float* Wk  = (const float*)d_in[3];
    const float* Wv  = (const float*)d_in[4];
    const float* W1  = (const float*)d_in[5];
    const float* W2  = (const float*)d_in[6];
    const int*   bs  = (const int*)d_in[7];
    int N = in_sizes[7];
    int G = in_sizes[1];
    float* out = (float*)d_out;
    int ntiles = (N + 127) / 128;

    const int nodes_smem = (FDIM * 132 + 4 * FDIM) * 8;                    // ~139 KB
    const int out_smem   = (FDIM * 68 + 64 * 132) * 4 + 256 * 4 + 128 * 8; // ~70.6 KB
    cudaFuncSetAttribute(k_nodes, cudaFuncAttributeMaxDynamicSharedMemorySize, nodes_smem);
    cudaFuncSetAttribute(k_out,   cudaFuncAttributeMaxDynamicSharedMemorySize, out_smem);

    k_zero<<<(G + 255) / 256, 256>>>(G);
    k_prep<<<1, 256>>>(Wq, Wk, psi, G);
    k_scan<<<(N + 7) / 8, 256>>>(oh, psi, bs, N);
    k_nodes<<<2 * MNODE, 128, nodes_smem>>>(Wv, W1, W2);
    k_cheb<<<32, 256>>>();
    int grid = 296;
    if (grid > ntiles) grid = ntiles;
    k_out<<<grid, 256, out_smem>>>(psi, bs, out, N, ntiles);
}

// round 6
// speedup vs baseline: 2.4964x; 1.1524x over previous
#include <cuda_runtime.h>
#include <cstdint>
#include <math.h>

#define NMAX 262144
#define GMAX 8192
#define EDIM 118
#define FDIM 128
#define KTAB 512          // intervals per branch (KTAB+1 grid points)
#define WPITCH 129        // odd pitch -> conflict-free smem dot reads

// ---------------- scratch (device globals; no allocation) ----------------
__device__ float g_y[NMAX];
__device__ float g_denom[GMAX];
__device__ float g_dot[EDIM * 2];
__device__ float g_amax;
__device__ float g_lin[2 * FDIM];                    // F'(0) per branch
__device__ float g_tab[2][KTAB + 1][FDIM];           // residual G(|att|) table

// ---------------- helpers ----------------
__device__ __forceinline__ float s1f(float x) {      // silu(x) - x/2, O(x^2), no cancellation
    return 0.5f * x * tanhf(0.5f * x);
}

// ---------------- kernel: zero denom + amax + dot table ----------------
__global__ void k_prep(const float* __restrict__ Wq, const float* __restrict__ Wk,
                       const float* __restrict__ psi, int G) {
    __shared__ float sk[256];
    __shared__ float smax[8];
    int t = threadIdx.x;
    for (int i = t; i < G; i += 256) g_denom[i] = 0.f;
    sk[t] = Wk[t];
    float m = 0.f;
    for (int i = t; i < G; i += 256) m = fmaxf(m, fabsf(psi[i]));
#pragma unroll
    for (int o = 16; o; o >>= 1) m = fmaxf(m, __shfl_xor_sync(0xffffffffu, m, o));
    if ((t & 31) == 0) smax[t >> 5] = m;
    __syncthreads();
    if (t == 0) {
        float mm = 1e-12f;
        for (int i = 0; i < 8; ++i) mm = fmaxf(mm, smax[i]);
        g_amax = mm;
    }
    if (t < EDIM) {
        float a0 = 0.f, a1 = 0.f;
#pragma unroll 8
        for (int f = 0; f < FDIM; ++f) {
            float w = Wq[f * EDIM + t];
            a0 = fmaf(w, sk[f], a0);
            a1 = fmaf(w, sk[FDIM + f], a1);
        }
        g_dot[t * 2 + 0] = a0;
        g_dot[t * 2 + 1] = a1;
    }
}

// ---------------- kernel: early-exit one-hot scan -> y, denom ----------------
__global__ void k_scan(const float* __restrict__ oh, const float* __restrict__ psi,
                       const int* __restrict__ bs, int N) {
    int warp = (blockIdx.x * blockDim.x + threadIdx.x) >> 5;
    int lane = threadIdx.x & 31;
    if (warp >= N) return;
    const float* row = oh + (size_t)warp * EDIM;
    float v0 = __ldcs(row + lane);
    float v1 = __ldcs(row + 32 + lane);
    unsigned m0 = __ballot_sync(0xffffffffu, v0 > 0.5f);
    unsigned m1 = __ballot_sync(0xffffffffu, v1 > 0.5f);
    int z;
    if (m0) z = __ffs(m0) - 1;
    else if (m1) z = 31 + __ffs(m1);
    else {
        float v2 = __ldcs(row + 64 + lane);
        int e3 = 96 + lane;
        float v3 = (e3 < EDIM) ? __ldcs(row + e3) : 0.f;
        m0 = __ballot_sync(0xffffffffu, v2 > 0.5f);
        m1 = __ballot_sync(0xffffffffu, v3 > 0.5f);
        z = m0 ? (63 + __ffs(m0)) : (95 + __ffs(m1));
    }
    if (lane == 0) {
        int g = bs[warp];
        float p = psi[g];
        int r = (p < 0.f) ? 1 : 0;
        float qk = g_dot[z * 2 + r] * 0.08838834764831845f;  // 1/sqrt(128)
        float y = (qk > 20.f) ? qk : log1pf(expf(qk));
        g_y[warp] = y;
        atomicAdd(&g_denom[g], y);
    }
}

// ---------------- kernel: build residual table + F'(0), all fp32 --------------
// Residual (cancellation-free):
//   hlin = W1@wv;  h(a) = 0.5a*hlin + W1@s1(a*wv)
//   F(a) - a*F1 = W2 @ [ 0.5*(W1@s1(a*wv)) + s1(h(a)) ]
//   F1 = wv + 0.25*(W2@hlin)
// grid: 130 blocks = 2 branches x 65 groups of 8 nodes; 128 threads (thread=feature)
__global__ void k_tab(const float* __restrict__ Wv, const float* __restrict__ W1,
                      const float* __restrict__ W2) {
    extern __shared__ float sm[];
    float* sW1 = sm;                       // [128][WPITCH]
    float* sW2 = sW1 + FDIM * WPITCH;      // [128][WPITCH]
    float* swv = sW2 + FDIM * WPITCH;      // [128]
    float* shl = swv + FDIM;               // [128] hlin
    float* ssv = shl + FDIM;               // [128] s1(a*wv)
    float* sbr = ssv + FDIM;               // [128] bracket
    int t = threadIdx.x;
    int b = blockIdx.x;
    int r = (b >= 65) ? 1 : 0;
    int i0 = (b - r * 65) * 8;
    float sgn = r ? -1.f : 1.f;

    // load weights (coalesced LDG, scalar STS into odd-pitch rows)
    const float4* W1v = (const float4*)W1;
    const float4* W2v = (const float4*)W2;
    for (int i = t; i < FDIM * 32; i += 128) {
        int row = i >> 5, c = (i & 31) * 4;
        float4 v1 = W1v[i];
        float* p = sW1 + row * WPITCH + c;
        p[0] = v1.x; p[1] = v1.y; p[2] = v1.z; p[3] = v1.w;
        float4 v2 = W2v[i];
        float* q = sW2 + row * WPITCH + c;
        q[0] = v2.x; q[1] = v2.y; q[2] = v2.z; q[3] = v2.w;
    }
    float wv = Wv[r * FDIM + t];
    swv[t] = wv;
    __syncthreads();

    // hlin[t] = dot(W1[t,:], wv)
    const float* w1row = sW1 + t * WPITCH;
    const float* w2row = sW2 + t * WPITCH;
    {
        float d0 = 0.f, d1 = 0.f, d2 = 0.f, d3 = 0.f;
#pragma unroll
        for (int k = 0; k < FDIM; k += 4) {
            d0 = fmaf(w1row[k],     swv[k],     d0);
            d1 = fmaf(w1row[k + 1], swv[k + 1], d1);
            d2 = fmaf(w1row[k + 2], swv[k + 2], d2);
            d3 = fmaf(w1row[k + 3], swv[k + 3], d3);
        }
        shl[t] = (d0 + d1) + (d2 + d3);
    }
    __syncthreads();
    float hlin = shl[t];

    if (i0 == 0) {  // F1 = wv + 0.25*(W2@hlin)
        float d0 = 0.f, d1 = 0.f, d2 = 0.f, d3 = 0.f;
#pragma unroll
        for (int k = 0; k < FDIM; k += 4) {
            d0 = fmaf(w2row[k],     shl[k],     d0);
            d1 = fmaf(w2row[k + 1], shl[k + 1], d1);
            d2 = fmaf(w2row[k + 2], shl[k + 2], d2);
            d3 = fmaf(w2row[k + 3], shl[k + 3], d3);
        }
        g_lin[r * FDIM + t] = fmaf(0.25f, (d0 + d1) + (d2 + d3), wv);
    }

    float amax = g_amax;
    for (int i = i0; i < i0 + 8 && i <= KTAB; ++i) {
        float mag = (i == 0) ? (amax * (1.f / 4096.f)) : (amax * (float)i * (1.f / KTAB));
        float a = sgn * mag;
        ssv[t] = s1f(a * wv);
        __syncthreads();
        float d0 = 0.f, d1 = 0.f, d2 = 0.f, d3 = 0.f;
#pragma unroll
        for (int k = 0; k < FDIM; k += 4) {
            d0 = fmaf(w1row[k],     ssv[k],     d0);
            d1 = fmaf(w1row[k + 1], ssv[k + 1], d1);
            d2 = fmaf(w1row[k + 2], ssv[k + 2], d2);
            d3 = fmaf(w1row[k + 3], ssv[k + 3], d3);
        }
        float tt = (d0 + d1) + (d2 + d3);          // W1@s1(a*wv)
        float h = fmaf(0.5f * a, hlin, tt);
        sbr[t] = fmaf(0.5f, tt, s1f(h));
        __syncthreads();
        float e0 = 0.f, e1 = 0.f, e2 = 0.f, e3 = 0.f;
#pragma unroll
        for (int k = 0; k < FDIM; k += 4) {
            e0 = fmaf(w2row[k],     sbr[k],     e0);
            e1 = fmaf(w2row[k + 1], sbr[k + 1], e1);
            e2 = fmaf(w2row[k + 2], sbr[k + 2], e2);
            e3 = fmaf(w2row[k + 3], sbr[k + 3], e3);
        }
        float resid = (e0 + e1) + (e2 + e3);
        g_tab[r][i][t] = resid / (a * a);
        __syncthreads();
    }
}

// ---------------- kernel: per-atom table lookup + linear-term epilogue --------
__global__ void __launch_bounds__(256)
k_out(const float* __restrict__ psi, const int* __restrict__ bs,
      float* __restrict__ out, int N) {
    __shared__ float sF1[2 * FDIM];
    int tid = threadIdx.x;
    sF1[tid] = g_lin[tid];
    __syncthreads();
    int n = blockIdx.x * 8 + (tid >> 5);
    if (n >= N) return;
    int lane = tid & 31;
    int g = bs[n];
    float p = psi[g];
    float att = p * g_y[n] / (g_denom[g] + 1e-6f);
    int r = (p < 0.f) ? 1 : 0;
    float x = fabsf(att) * ((float)KTAB / g_amax);
    int j = (int)x;
    if (j > KTAB - 1) j = KTAB - 1;
    float w = x - (float)j;
    const float4* row = (const float4*)&g_tab[r][j][0];
    float4 a0 = __ldg(row + lane);
    float4 a1 = __ldg(row + 32 + lane);
    float4 f1 = ((const float4*)(sF1 + r * FDIM))[lane];
    float att2 = att * att;
    float4 o;
    o.x = fmaf(att, f1.x, att2 * fmaf(w, a1.x - a0.x, a0.x));
    o.y = fmaf(att, f1.y, att2 * fmaf(w, a1.y - a0.y, a0.y));
    o.z = fmaf(att, f1.z, att2 * fmaf(w, a1.z - a0.z, a0.z));
    o.w = fmaf(att, f1.w, att2 * fmaf(w, a1.w - a0.w, a0.w));
    ((float4*)out)[(size_t)n * 32 + lane] = o;
}

// ---------------- launch ----------------
extern "C" void kernel_launch(void* const* d_in, const int* in_sizes, int n_in,
                              void* d_out, int out_size) {
    const float* oh  = (const float*)d_in[0];
    const float* psi = (const float*)d_in[1];
    const float* Wq  = (const float*)d_in[2];
    const float* Wk  = (const float*)d_in[3];
    const float* Wv  = (const float*)d_in[4];
    const float* W1  = (const float*)d_in[5];
    const float* W2  = (const float*)d_in[6];
    const int*   bs  = (const int*)d_in[7];
    int N = in_sizes[7];
    int G = in_sizes[1];
    float* out = (float*)d_out;

    const int tab_smem = (2 * FDIM * WPITCH + 4 * FDIM) * 4;   // ~134 KB
    cudaFuncSetAttribute(k_tab, cudaFuncAttributeMaxDynamicSharedMemorySize, tab_smem);

    k_prep<<<1, 256>>>(Wq, Wk, psi, G);
    k_scan<<<(N + 7) / 8, 256>>>(oh, psi, bs, N);
    k_tab<<<130, 128, tab_smem>>>(Wv, W1, W2);
    k_out<<<(N + 7) / 8, 256>>>(psi, bs, out, N);
}